// round 1
// baseline (speedup 1.0000x reference)
#include <cuda_runtime.h>
#include <cstdint>

// ---------------------------------------------------------------------------
// SuperLoss:  tau = mean(loss)
//             y   = 0.5 * max(-2/e, (l - tau)/lam),  lam = 0.1
//             w   = W0(y),  sigma = exp(-w)
//             out = (l - tau)*sigma + lam*w^2
//
// Key substitution: u = e*y + 1 = max(0, 1 + C*(l - tau)),  C = e/(2*lam).
// w and sigma are smooth 1-D functions of u on [0, 16). We tabulate them on a
// float-exponent-indexed grid (32 octaves [2^-28, 16), 64 cells/octave) with
// linear interpolation — resolves the sqrt branch singularity at u -> 0 and
// needs ZERO MUFU ops in the hot loop (MUFU is only 0.5 op/cyc/SM on B300).
// u == 0 (the clamp, ~42% of data) gives exactly w = -1, sigma = e.
// ---------------------------------------------------------------------------

#define C_SLOPE   13.591409142295225f   // e / (2*0.1)
#define INV_E     0.36787944117144233f
#define E_CONST   2.718281828459045f
#define LAMF      0.1f
#define U_MIN     3.725290298461914e-9f // 2^-28
#define U_MAXC    15.999999f
#define IDX_OFF   6336                  // (127-28) << 6
#define LUT_N     2048                  // 32 octaves * 64
#define T_INV     7.62939453125e-6f     // 1/2^17

#define RED_BLOCKS 1024
#define RED_THREADS 256
#define MAP_BLOCKS 1036                 // 148 SMs * 7 (32KB smem/block)
#define MAP_THREADS 256

__device__ float4 g_lut[LUT_N];
__device__ float  g_partial[RED_BLOCKS];
__device__ float  g_tau;

// ---------------------------------------------------------------------------
// Accurate W0 from u = e*y + 1 (matches the reference's fp32 Halley scheme)
// ---------------------------------------------------------------------------
__device__ __forceinline__ float w0_from_u(float u)
{
    float p  = sqrtf(fmaxf(2.0f * u, 0.0f));
    float wb = -1.0f + p - p * p * (1.0f / 3.0f) + (11.0f / 72.0f) * p * p * p;
    float y  = (u - 1.0f) * INV_E;
    float w  = (y < 0.0f) ? wb : log1pf(y);
#pragma unroll
    for (int it = 0; it < 8; ++it) {
        float ew   = expf(w);
        float f    = fmaf(w, ew, -y);
        float wp1  = w + 1.0f;
        float safe = (fabsf(wp1) < 1e-6f) ? 1e-6f : wp1;
        float den  = ew * wp1 - (w + 2.0f) * f / (2.0f * safe);
        den        = (fabsf(den) < 1e-12f) ? 1e-12f : den;
        w          = w - f / den;
    }
    return w;
}

// ---------------------------------------------------------------------------
// K1: partial sums (deterministic two-stage mean)
// ---------------------------------------------------------------------------
__global__ void __launch_bounds__(RED_THREADS)
reduce_kernel(const float* __restrict__ in, int n)
{
    int tid    = blockIdx.x * blockDim.x + threadIdx.x;
    int stride = gridDim.x * blockDim.x;
    int n4     = n >> 2;
    const float4* in4 = reinterpret_cast<const float4*>(in);

    float sum = 0.0f;
    for (int i = tid; i < n4; i += stride) {
        float4 v = in4[i];
        sum += (v.x + v.y) + (v.z + v.w);
    }
    for (int i = (n4 << 2) + tid; i < n; i += stride)
        sum += in[i];

#pragma unroll
    for (int o = 16; o > 0; o >>= 1)
        sum += __shfl_xor_sync(0xFFFFFFFFu, sum, o);

    __shared__ float ws[RED_THREADS / 32];
    if ((threadIdx.x & 31) == 0) ws[threadIdx.x >> 5] = sum;
    __syncthreads();
    if (threadIdx.x < (RED_THREADS / 32)) {
        float s = ws[threadIdx.x];
#pragma unroll
        for (int o = (RED_THREADS / 64); o > 0; o >>= 1)
            s += __shfl_xor_sync(0xFFu, s, o);
        if (threadIdx.x == 0) g_partial[blockIdx.x] = s;
    }
}

// ---------------------------------------------------------------------------
// K2: block 0 -> final mean (double accumulation); blocks 1..7 -> fill LUT
// ---------------------------------------------------------------------------
__global__ void __launch_bounds__(256)
finalize_kernel(int n)
{
    if (blockIdx.x == 0) {
        double s = 0.0;
        for (int i = threadIdx.x; i < RED_BLOCKS; i += 256)
            s += (double)g_partial[i];
#pragma unroll
        for (int o = 16; o > 0; o >>= 1)
            s += __shfl_xor_sync(0xFFFFFFFFu, s, o);
        __shared__ double ws[8];
        if ((threadIdx.x & 31) == 0) ws[threadIdx.x >> 5] = s;
        __syncthreads();
        if (threadIdx.x < 8) {
            double t = ws[threadIdx.x];
#pragma unroll
            for (int o = 4; o > 0; o >>= 1)
                t += __shfl_xor_sync(0xFFu, t, o);
            if (threadIdx.x == 0) g_tau = (float)(t / (double)n);
        }
    } else {
        int e = (blockIdx.x - 1) * 256 + threadIdx.x;   // 7 blocks * 256 = 1792; pad to 2048
        // cover all 2048 entries: blocks 1..7 handle 0..1791, block 7 also wraps
        for (; e < LUT_N; e += 7 * 256) {
            int oct = e >> 6;
            int j   = e & 63;
            unsigned bits = ((unsigned)(oct + 99) << 23) | ((unsigned)j << 17);
            float u0 = __uint_as_float(bits);
            float u1 = __uint_as_float(bits + 0x20000u);  // next node (1<<17)
            float w0 = w0_from_u(u0);
            float w1 = w0_from_u(u1);
            float s0 = expf(-w0);
            float s1 = expf(-w1);
            g_lut[e] = make_float4(w0, (w1 - w0) * T_INV, s0, (s1 - s0) * T_INV);
        }
    }
}

// ---------------------------------------------------------------------------
// K3: elementwise map. No MUFU, no branches in the hot loop.
// ---------------------------------------------------------------------------
__device__ __forceinline__ float superloss_elem(float l, float tau,
                                                const float4* __restrict__ slut)
{
    float d  = l - tau;
    float u  = fmaf(C_SLOPE, d, 1.0f);
    bool  lo = (u < U_MIN);                        // clamp region (u<=0 and tiny u)
    float uc = fminf(fmaxf(u, U_MIN), U_MAXC);
    unsigned ub = __float_as_uint(uc);
    int   idx = (int)(ub >> 17) - IDX_OFF;         // exponent<<6 | top-6 mantissa
    float t   = (float)(ub & 0x1FFFFu);            // low 17 mantissa bits
    float4 e  = slut[idx];
    float w   = fmaf(t, e.y, e.x);
    float s   = fmaf(t, e.w, e.z);
    w = lo ? -1.0f : w;
    s = lo ? (float)E_CONST : s;
    return fmaf(d, s, LAMF * w * w);               // (l-tau)*sigma + lam*w^2
}

__global__ void __launch_bounds__(MAP_THREADS)
map_kernel(const float* __restrict__ in, float* __restrict__ out, int n)
{
    __shared__ float4 slut[LUT_N];                 // 32 KB
    for (int i = threadIdx.x; i < LUT_N; i += blockDim.x)
        slut[i] = g_lut[i];
    __syncthreads();

    float tau = g_tau;

    int tid    = blockIdx.x * blockDim.x + threadIdx.x;
    int stride = gridDim.x * blockDim.x;
    int n4     = n >> 2;
    const float4* in4  = reinterpret_cast<const float4*>(in);
    float4*       out4 = reinterpret_cast<float4*>(out);

    for (int i = tid; i < n4; i += stride) {
        float4 v = in4[i];
        float4 r;
        r.x = superloss_elem(v.x, tau, slut);
        r.y = superloss_elem(v.y, tau, slut);
        r.z = superloss_elem(v.z, tau, slut);
        r.w = superloss_elem(v.w, tau, slut);
        out4[i] = r;
    }
    for (int i = (n4 << 2) + tid; i < n; i += stride)
        out[i] = superloss_elem(in[i], tau, slut);
}

// ---------------------------------------------------------------------------
extern "C" void kernel_launch(void* const* d_in, const int* in_sizes, int n_in,
                              void* d_out, int out_size)
{
    const float* loss = (const float*)d_in[0];
    float*       out  = (float*)d_out;
    int n = in_sizes[0];

    reduce_kernel<<<RED_BLOCKS, RED_THREADS>>>(loss, n);
    finalize_kernel<<<8, 256>>>(n);
    map_kernel<<<MAP_BLOCKS, MAP_THREADS>>>(loss, out, n);
}

// round 2
// speedup vs baseline: 1.0838x; 1.0838x over previous
#include <cuda_runtime.h>
#include <cstdint>

// ---------------------------------------------------------------------------
// SuperLoss:  tau = mean(loss)
//             y   = 0.5 * max(-2/e, (l - tau)/lam),  lam = 0.1
//             w   = W0(y),  sigma = exp(-w)
//             out = (l - tau)*sigma + lam*w^2
//
// u = e*y + 1 = max(0, 1 + C*(l - tau)), C = e/(2*lam). w, sigma tabulated
// over u on a float-exponent grid (32 octaves, 64 cells each) with linear
// interp -> zero MUFU in the hot loop. Clamp region (u ~ 0, ~43% of data)
// is exact (w=-1, sigma=e) and skips the LDS entirely (predicated off).
//
// L2 strategy: input (128MB) ~ L2 (126MB). Writes use __stcs (evict-first)
// so they don't displace the input; the map pass walks DESCENDING so it
// consumes the reduce pass's MRU tail first (no LRU thrash cascade). In
// graph-replay steady state both input reads are largely L2-served and DRAM
// carries mostly the output write.
// ---------------------------------------------------------------------------

#define C_SLOPE   13.591409142295225f   // e / (2*0.1)
#define INV_E     0.36787944117144233f
#define E_CONST   2.718281828459045f
#define LAMF      0.1f
#define U_MIN     3.725290298461914e-9f // 2^-28
#define U_MAXC    15.999999f
#define IDX_OFF   6336                  // (127-28) << 6
#define LUT_N     2048                  // 32 octaves * 64 cells
#define T_INV     7.62939453125e-6f     // 1/2^17

#define RED_BLOCKS  1024
#define LUT_BLOCKS  8
#define RED_THREADS 256
#define MAP_BLOCKS  1036                // 148 SMs * 7 (32KB smem/block)
#define MAP_THREADS 256

__device__ float4   g_lut[LUT_N];
__device__ float    g_partial[RED_BLOCKS];
__device__ float    g_tau;
__device__ unsigned g_ctr = 0;

// ---------------------------------------------------------------------------
// Accurate W0 from u = e*y + 1 (matches the reference's fp32 Halley scheme)
// ---------------------------------------------------------------------------
__device__ __forceinline__ float w0_from_u(float u)
{
    float p  = sqrtf(fmaxf(2.0f * u, 0.0f));
    float wb = -1.0f + p - p * p * (1.0f / 3.0f) + (11.0f / 72.0f) * p * p * p;
    float y  = (u - 1.0f) * INV_E;
    float w  = (y < 0.0f) ? wb : log1pf(y);
#pragma unroll
    for (int it = 0; it < 8; ++it) {
        float ew   = expf(w);
        float f    = fmaf(w, ew, -y);
        float wp1  = w + 1.0f;
        float safe = (fabsf(wp1) < 1e-6f) ? 1e-6f : wp1;
        float den  = ew * wp1 - (w + 2.0f) * f / (2.0f * safe);
        den        = (fabsf(den) < 1e-12f) ? 1e-12f : den;
        w          = w - f / den;
    }
    return w;
}

// ---------------------------------------------------------------------------
// K1: partial sums + LUT fill (extra blocks) + last-block tau finalize
// ---------------------------------------------------------------------------
__global__ void __launch_bounds__(RED_THREADS)
reduce_prep_kernel(const float* __restrict__ in, int n)
{
    // --- LUT-filling blocks (tau-independent, overlapped with the reduce) ---
    if (blockIdx.x >= RED_BLOCKS) {
        int e = (blockIdx.x - RED_BLOCKS) * RED_THREADS + threadIdx.x; // 0..2047
        if (e < LUT_N) {
            int oct = e >> 6;
            int j   = e & 63;
            unsigned bits = ((unsigned)(oct + 99) << 23) | ((unsigned)j << 17);
            float u0 = __uint_as_float(bits);
            float u1 = __uint_as_float(bits + 0x20000u);  // next node (+1<<17)
            float w0 = w0_from_u(u0);
            float w1 = w0_from_u(u1);
            float s0 = expf(-w0);
            float s1 = expf(-w1);
            g_lut[e] = make_float4(w0, (w1 - w0) * T_INV, s0, (s1 - s0) * T_INV);
        }
        return;
    }

    // --- reduction blocks ---
    int tid    = blockIdx.x * blockDim.x + threadIdx.x;
    int stride = RED_BLOCKS * RED_THREADS;
    int n4     = n >> 2;
    const float4* in4 = reinterpret_cast<const float4*>(in);

    float s0 = 0.0f, s1 = 0.0f;
    int i = tid;
    for (; i + stride < n4; i += 2 * stride) {
        float4 a = in4[i];
        float4 b = in4[i + stride];
        s0 += (a.x + a.y) + (a.z + a.w);
        s1 += (b.x + b.y) + (b.z + b.w);
    }
    if (i < n4) {
        float4 a = in4[i];
        s0 += (a.x + a.y) + (a.z + a.w);
    }
    for (int k = (n4 << 2) + tid; k < n; k += stride)
        s0 += in[k];
    float sum = s0 + s1;

#pragma unroll
    for (int o = 16; o > 0; o >>= 1)
        sum += __shfl_xor_sync(0xFFFFFFFFu, sum, o);

    __shared__ float ws[RED_THREADS / 32];
    if ((threadIdx.x & 31) == 0) ws[threadIdx.x >> 5] = sum;
    __syncthreads();
    if (threadIdx.x == 0) {
        float s = ws[0];
#pragma unroll
        for (int w = 1; w < RED_THREADS / 32; ++w) s += ws[w];
        g_partial[blockIdx.x] = s;
    }

    // --- last block computes tau (double accumulation, deterministic) ---
    __shared__ bool s_last;
    __threadfence();
    if (threadIdx.x == 0) {
        unsigned t = atomicAdd(&g_ctr, 1u);
        s_last = (t == RED_BLOCKS - 1);
    }
    __syncthreads();
    if (s_last) {
        double acc = 0.0;
        for (int k = threadIdx.x; k < RED_BLOCKS; k += RED_THREADS)
            acc += (double)g_partial[k];
#pragma unroll
        for (int o = 16; o > 0; o >>= 1)
            acc += __shfl_xor_sync(0xFFFFFFFFu, acc, o);
        __shared__ double wd[RED_THREADS / 32];
        if ((threadIdx.x & 31) == 0) wd[threadIdx.x >> 5] = acc;
        __syncthreads();
        if (threadIdx.x == 0) {
            double t = wd[0];
#pragma unroll
            for (int w = 1; w < RED_THREADS / 32; ++w) t += wd[w];
            g_tau = (float)(t / (double)n);
            g_ctr = 0;   // reset for next graph replay (deterministic)
        }
    }
}

// ---------------------------------------------------------------------------
// K2: elementwise map. No MUFU; LDS predicated off for clamped lanes;
//     descending walk; streaming (evict-first) stores.
// ---------------------------------------------------------------------------
__device__ __forceinline__ float superloss_elem(float l, float tau,
                                                const float4* __restrict__ slut)
{
    float d  = l - tau;
    float u  = fmaf(C_SLOPE, d, 1.0f);
    float4 e = make_float4(-1.0f, 0.0f, E_CONST, 0.0f);  // clamp: w=-1, sigma=e
    float t  = 0.0f;
    if (u >= U_MIN) {                                    // predicated LDS path
        float uc = fminf(u, U_MAXC);
        unsigned ub = __float_as_uint(uc);
        int idx = (int)(ub >> 17) - IDX_OFF;
        t = (float)(ub & 0x1FFFFu);
        e = slut[idx];
    }
    float w = fmaf(t, e.y, e.x);
    float s = fmaf(t, e.w, e.z);
    return fmaf(d, s, LAMF * w * w);
}

__global__ void __launch_bounds__(MAP_THREADS)
map_kernel(const float* __restrict__ in, float* __restrict__ out, int n)
{
    __shared__ float4 slut[LUT_N];                       // 32 KB
    for (int i = threadIdx.x; i < LUT_N; i += blockDim.x)
        slut[i] = g_lut[i];
    __syncthreads();

    float tau = g_tau;

    int tid    = blockIdx.x * blockDim.x + threadIdx.x;
    int stride = gridDim.x * blockDim.x;
    int n4     = n >> 2;
    const float4* in4  = reinterpret_cast<const float4*>(in);
    float4*       out4 = reinterpret_cast<float4*>(out);

    // descending walk: consume the reduce pass's MRU tail of L2 first
    for (int i = tid; i < n4; i += stride) {
        int j = n4 - 1 - i;
        float4 v = in4[j];
        float4 r;
        r.x = superloss_elem(v.x, tau, slut);
        r.y = superloss_elem(v.y, tau, slut);
        r.z = superloss_elem(v.z, tau, slut);
        r.w = superloss_elem(v.w, tau, slut);
        __stcs(&out4[j], r);                             // evict-first store
    }
    for (int k = (n4 << 2) + tid; k < n; k += stride)
        __stcs(&out[k], superloss_elem(in[k], tau, slut));
}

// ---------------------------------------------------------------------------
extern "C" void kernel_launch(void* const* d_in, const int* in_sizes, int n_in,
                              void* d_out, int out_size)
{
    const float* loss = (const float*)d_in[0];
    float*       out  = (float*)d_out;
    int n = in_sizes[0];

    reduce_prep_kernel<<<RED_BLOCKS + LUT_BLOCKS, RED_THREADS>>>(loss, n);
    map_kernel<<<MAP_BLOCKS, MAP_THREADS>>>(loss, out, n);
}

// round 3
// speedup vs baseline: 1.4437x; 1.3321x over previous
#include <cuda_runtime.h>
#include <cstdint>

// ---------------------------------------------------------------------------
// SuperLoss:  tau = mean(loss)
//             y   = 0.5 * max(-2/e, (l - tau)/lam),  lam = 0.1
//             w   = W0(y),  sigma = exp(-w),  out = (l-tau)*sigma + lam*ln(sigma)^2
//
// Identity: w e^w = y  =>  sigma = w/y, and (l-tau) = 2*lam*y off-clamp, so
//     out = 2*lam*w + lam*w^2 = lam*w*(w+2)          (unclamped branch)
//     out = e*(l-tau) + lam                           (clamp: w=-1, sigma=e)
// Only w is needed -> float2 LUT (w0, slope) over u = max(0, 1 + C*(l-tau)),
// indexed by float exponent+mantissa bits (geometric grid resolves the
// sqrt branch singularity at u->0). Zero MUFU in the hot loop; LDS.64 only.
// ---------------------------------------------------------------------------

#define C_SLOPE   13.591409142295225f   // e / (2*0.1)
#define INV_E     0.36787944117144233f
#define E_CONST   2.718281828459045f
#define LAMF      0.1f
#define U_MIN     3.725290298461914e-9f // 2^-28
#define U_MAXC    15.999999f
#define IDX_OFF   6336                  // (127-28) << 6
#define LUT_N     2048                  // 32 octaves * 64 cells
#define T_INV     7.62939453125e-6f     // 1/2^17

#define RED_BLOCKS  1024
#define LUT_BLOCKS  8
#define RED_THREADS 256
#define MAP_BLOCKS  888                 // 148 SMs * 6
#define MAP_THREADS 256

__device__ float2   g_lut[LUT_N];
__device__ float    g_partial[RED_BLOCKS];
__device__ float    g_tau;
__device__ unsigned g_ctr = 0;

// ---------------------------------------------------------------------------
// Accurate W0 from u = e*y + 1 (matches the reference's fp32 Halley scheme)
// ---------------------------------------------------------------------------
__device__ __forceinline__ float w0_from_u(float u)
{
    float p  = sqrtf(fmaxf(2.0f * u, 0.0f));
    float wb = -1.0f + p - p * p * (1.0f / 3.0f) + (11.0f / 72.0f) * p * p * p;
    float y  = (u - 1.0f) * INV_E;
    float w  = (y < 0.0f) ? wb : log1pf(y);
#pragma unroll
    for (int it = 0; it < 8; ++it) {
        float ew   = expf(w);
        float f    = fmaf(w, ew, -y);
        float wp1  = w + 1.0f;
        float safe = (fabsf(wp1) < 1e-6f) ? 1e-6f : wp1;
        float den  = ew * wp1 - (w + 2.0f) * f / (2.0f * safe);
        den        = (fabsf(den) < 1e-12f) ? 1e-12f : den;
        w          = w - f / den;
    }
    return w;
}

// ---------------------------------------------------------------------------
// K1: partial sums + LUT fill (extra blocks) + last-block tau finalize
// ---------------------------------------------------------------------------
__global__ void __launch_bounds__(RED_THREADS)
reduce_prep_kernel(const float* __restrict__ in, int n)
{
    if (blockIdx.x >= RED_BLOCKS) {                     // LUT blocks
        int e = (blockIdx.x - RED_BLOCKS) * RED_THREADS + threadIdx.x;
        if (e < LUT_N) {
            int oct = e >> 6;
            int j   = e & 63;
            unsigned bits = ((unsigned)(oct + 99) << 23) | ((unsigned)j << 17);
            float u0 = __uint_as_float(bits);
            float u1 = __uint_as_float(bits + 0x20000u);
            float w0 = w0_from_u(u0);
            float w1 = w0_from_u(u1);
            g_lut[e] = make_float2(w0, (w1 - w0) * T_INV);
        }
        return;
    }

    int tid    = blockIdx.x * blockDim.x + threadIdx.x;
    int stride = RED_BLOCKS * RED_THREADS;
    int n4     = n >> 2;
    const float4* in4 = reinterpret_cast<const float4*>(in);

    float s0 = 0.0f, s1 = 0.0f, s2 = 0.0f, s3 = 0.0f;
    int i = tid;
    for (; i + 3 * stride < n4; i += 4 * stride) {
        float4 a = in4[i];
        float4 b = in4[i + stride];
        float4 c = in4[i + 2 * stride];
        float4 d = in4[i + 3 * stride];
        s0 += (a.x + a.y) + (a.z + a.w);
        s1 += (b.x + b.y) + (b.z + b.w);
        s2 += (c.x + c.y) + (c.z + c.w);
        s3 += (d.x + d.y) + (d.z + d.w);
    }
    for (; i < n4; i += stride) {
        float4 a = in4[i];
        s0 += (a.x + a.y) + (a.z + a.w);
    }
    for (int k = (n4 << 2) + tid; k < n; k += stride)
        s0 += in[k];
    float sum = (s0 + s1) + (s2 + s3);

#pragma unroll
    for (int o = 16; o > 0; o >>= 1)
        sum += __shfl_xor_sync(0xFFFFFFFFu, sum, o);

    __shared__ float ws[RED_THREADS / 32];
    if ((threadIdx.x & 31) == 0) ws[threadIdx.x >> 5] = sum;
    __syncthreads();
    if (threadIdx.x == 0) {
        float s = ws[0];
#pragma unroll
        for (int w = 1; w < RED_THREADS / 32; ++w) s += ws[w];
        g_partial[blockIdx.x] = s;
    }

    __shared__ bool s_last;
    __threadfence();
    if (threadIdx.x == 0) {
        unsigned t = atomicAdd(&g_ctr, 1u);
        s_last = (t == RED_BLOCKS - 1);
    }
    __syncthreads();
    if (s_last) {
        double acc = 0.0;
        for (int k = threadIdx.x; k < RED_BLOCKS; k += RED_THREADS)
            acc += (double)g_partial[k];
#pragma unroll
        for (int o = 16; o > 0; o >>= 1)
            acc += __shfl_xor_sync(0xFFFFFFFFu, acc, o);
        __shared__ double wd[RED_THREADS / 32];
        if ((threadIdx.x & 31) == 0) wd[threadIdx.x >> 5] = acc;
        __syncthreads();
        if (threadIdx.x == 0) {
            double t = wd[0];
#pragma unroll
            for (int w = 1; w < RED_THREADS / 32; ++w) t += wd[w];
            g_tau = (float)(t / (double)n);
            g_ctr = 0;                                   // reset for next replay
        }
    }
}

// ---------------------------------------------------------------------------
// K2: elementwise map. out = lam*w*(w+2)  |  e*d + lam (clamp). LDS.64 only.
// ---------------------------------------------------------------------------
__device__ __forceinline__ float superloss_elem(float l, float tau,
                                                const float2* __restrict__ slut)
{
    float d = l - tau;
    float u = fmaf(C_SLOPE, d, 1.0f);
    float out_c = fmaf(E_CONST, d, LAMF);                // clamp-branch value
    if (u < U_MIN) return out_c;
    float uc = fminf(u, U_MAXC);
    unsigned ub = __float_as_uint(uc);
    int   idx = (int)(ub >> 17) - IDX_OFF;
    float t   = (float)(int)(ub & 0x1FFFFu);
    float2 e  = slut[idx];
    float w   = fmaf(t, e.y, e.x);
    float lw  = LAMF * w;
    return fmaf(lw, w, lw + lw);                         // lam*w^2 + 2*lam*w
}

__global__ void __launch_bounds__(MAP_THREADS, 6)
map_kernel(const float* __restrict__ in, float* __restrict__ out, int n)
{
    __shared__ float2 slut[LUT_N];                       // 16 KB
    {
        const float4* src = reinterpret_cast<const float4*>(g_lut);
        float4* dst = reinterpret_cast<float4*>(slut);
        for (int i = threadIdx.x; i < LUT_N / 2; i += blockDim.x)
            dst[i] = src[i];
    }
    __syncthreads();

    float tau = g_tau;

    int tid    = blockIdx.x * blockDim.x + threadIdx.x;
    int stride = gridDim.x * blockDim.x;
    int n4     = n >> 2;
    const float4* in4  = reinterpret_cast<const float4*>(in);
    float4*       out4 = reinterpret_cast<float4*>(out);

    // descending walk (consume reduce pass's MRU L2 tail), 2-way MLP
    for (int i = tid; i < n4; i += 2 * stride) {
        int  j0   = n4 - 1 - i;
        bool has2 = (i + stride) < n4;
        int  j1   = has2 ? (j0 - stride) : j0;

        float4 v0 = in4[j0];
        float4 v1 = in4[j1];

        float4 r0, r1;
        r0.x = superloss_elem(v0.x, tau, slut);
        r0.y = superloss_elem(v0.y, tau, slut);
        r0.z = superloss_elem(v0.z, tau, slut);
        r0.w = superloss_elem(v0.w, tau, slut);
        r1.x = superloss_elem(v1.x, tau, slut);
        r1.y = superloss_elem(v1.y, tau, slut);
        r1.z = superloss_elem(v1.z, tau, slut);
        r1.w = superloss_elem(v1.w, tau, slut);

        __stcs(&out4[j0], r0);
        if (has2) __stcs(&out4[j1], r1);
    }
    for (int k = (n4 << 2) + tid; k < n; k += stride)
        __stcs(&out[k], superloss_elem(in[k], tau, slut));
}

// ---------------------------------------------------------------------------
extern "C" void kernel_launch(void* const* d_in, const int* in_sizes, int n_in,
                              void* d_out, int out_size)
{
    const float* loss = (const float*)d_in[0];
    float*       out  = (float*)d_out;
    int n = in_sizes[0];

    reduce_prep_kernel<<<RED_BLOCKS + LUT_BLOCKS, RED_THREADS>>>(loss, n);
    map_kernel<<<MAP_BLOCKS, MAP_THREADS>>>(loss, out, n);
}